// round 9
// baseline (speedup 1.0000x reference)
#include <cuda_runtime.h>
#include <stdint.h>

// Canny magnitude, fully fused, float4 + rolling-window vertical reuse.
// gray -> 5x5 separable gaussian (reflect) -> sobel (edge clamp) -> magnitude
// -> comparison octant -> 8-dir NMS (zero pad) -> mag * is_max
// Input (16,3,512,512) f32, output (16,1,512,512) f32.

#define H_IMG 512
#define W_IMG 512
#define PLANE (H_IMG * W_IMG)
#define TX 64
#define TY 32
#define NT 256

#define GW 72   // gray width/stride  (halo 4)  = 18 float4
#define GH 40
#define HW 68   // h-blur width/stride (halo 2) = 17 float4
#define BH 36   // blur rows
#define BW 72   // blur stride (PADDED; valid cols 0..67)
#define MH 34
#define MW 68   // mag stride (valid cols 0..65; 66,67 pad = 0)

// idx -> linear NMS offset in mag tile (stride MW=68):
// (0,1)(-1,1)(-1,0)(-1,-1)(0,-1)(1,-1)(1,0)(1,1)
__constant__ int c_nms_off[8] = { 1, -67, -68, -69, -1, 67, 68, 69 };

__device__ __forceinline__ int reflect_idx(int i, int n) {
    if (i < 0) i = -i;
    if (i >= n) i = 2 * n - 2 - i;
    return i;
}

__device__ __forceinline__ int octant(float gx, float gy) {
    // round(atan2(gy,gx)/45deg) mod 8 via comparisons
    float ax = fabsf(gx), ay = fabsf(gy);
    int o = (ay > 0.4142135623730950f * ax) + (ay > 2.4142135623730950f * ax);
    if (gx < 0.0f) return (gy < 0.0f) ? (4 + o) : (4 - o);
    else           return (gy < 0.0f) ? ((8 - o) & 7) : o;
}

#define GW0 0.054488684548643f
#define GW1 0.244201342003233f
#define GW2 0.402619946896247f

__global__ void __launch_bounds__(NT)
canny_fused_kernel(const float* __restrict__ in, float* __restrict__ out) {
    __shared__ __align__(16) float sA[GH * GW];   // gray; later mag (MH*MW)
    __shared__ __align__(16) float sB[GH * HW];   // htmp; later dir bytes
    __shared__ __align__(16) float sC[BH * BW];   // blurred (padded stride)

    float*    sM  = sA;
    int8_t*   sD  = (int8_t*)sB;
    uint32_t* sDw = (uint32_t*)sB;

    const int tid = threadIdx.x;
    const int x0  = blockIdx.x * TX;
    const int y0  = blockIdx.y * TY;
    const int b   = blockIdx.z;

    const float* base = in + (size_t)b * 3 * PLANE;

    const bool interior = (x0 >= 4) && (x0 + TX + 4 <= W_IMG) &&
                          (y0 >= 4) && (y0 + TY + 4 <= H_IMG);

    // ---- Phase 1: grayscale into sA (GH x GW) ----
    if (interior) {
        const float* p = base + (y0 - 4) * W_IMG + (x0 - 4);  // 16B aligned
        #pragma unroll 1
        for (int i = tid; i < GH * 18; i += NT) {
            int r = i / 18, c4 = (i - r * 18) * 4;
            const float* q = p + r * W_IMG + c4;
            float4 R = *(const float4*)q;
            float4 G = *(const float4*)(q + PLANE);
            float4 B = *(const float4*)(q + 2 * PLANE);
            float4 o;
            o.x = fmaf(0.1495f, R.x, fmaf(0.2935f, G.x, fmaf(0.057f, B.x, 0.5f)));
            o.y = fmaf(0.1495f, R.y, fmaf(0.2935f, G.y, fmaf(0.057f, B.y, 0.5f)));
            o.z = fmaf(0.1495f, R.z, fmaf(0.2935f, G.z, fmaf(0.057f, B.z, 0.5f)));
            o.w = fmaf(0.1495f, R.w, fmaf(0.2935f, G.w, fmaf(0.057f, B.w, 0.5f)));
            *(float4*)(sA + r * GW + c4) = o;
        }
    } else {
        #pragma unroll 1
        for (int i = tid; i < GH * 18; i += NT) {
            int r = i / 18, c4 = (i - r * 18) * 4;
            int yy = reflect_idx(y0 - 4 + r, H_IMG) * W_IMG;
            float o[4];
            #pragma unroll
            for (int j = 0; j < 4; j++) {
                int off = yy + reflect_idx(x0 - 4 + c4 + j, W_IMG);
                o[j] = fmaf(0.1495f, base[off],
                       fmaf(0.2935f, base[off + PLANE],
                       fmaf(0.057f,  base[off + 2 * PLANE], 0.5f)));
            }
            *(float4*)(sA + r * GW + c4) = make_float4(o[0], o[1], o[2], o[3]);
        }
    }
    __syncthreads();

    // ---- Phase 2: horizontal blur sA -> sB, 2-f4 units (GH x 9) ----
    #pragma unroll 1
    for (int i = tid; i < GH * 9; i += NT) {
        int r = i / 9, c4 = (i - r * 9) * 8;
        const float* g = sA + r * GW + c4;
        float4 a = *(const float4*)g;
        float4 m = *(const float4*)(g + 4);
        float4 o;
        o.x = GW0 * (a.x + m.x) + GW1 * (a.y + a.w) + GW2 * a.z;
        o.y = GW0 * (a.y + m.y) + GW1 * (a.z + m.x) + GW2 * a.w;
        o.z = GW0 * (a.z + m.z) + GW1 * (a.w + m.y) + GW2 * m.x;
        o.w = GW0 * (a.w + m.w) + GW1 * (m.x + m.z) + GW2 * m.y;
        *(float4*)(sB + r * HW + c4) = o;
        if (c4 < 64) {
            float4 e = *(const float4*)(g + 8);
            float4 o2;
            o2.x = GW0 * (m.x + e.x) + GW1 * (m.y + m.w) + GW2 * m.z;
            o2.y = GW0 * (m.y + e.y) + GW1 * (m.z + e.x) + GW2 * m.w;
            o2.z = GW0 * (m.z + e.z) + GW1 * (m.w + e.y) + GW2 * e.x;
            o2.w = GW0 * (m.w + e.w) + GW1 * (e.x + e.z) + GW2 * e.y;
            *(float4*)(sB + r * HW + c4 + 4) = o2;
        }
    }
    __syncthreads();

    // ---- Phase 3: vertical blur sB -> sC, rolling 5-row window ----
    // 17 col-groups x 12 chunks of 3 rows = 204 units (single pass)
    if (tid < 17 * 12) {
        int ch = tid / 17;
        int cg = tid - ch * 17;
        int r0 = ch * 3;
        const float* h = sB + r0 * HW + cg * 4;
        float4 v0 = *(const float4*)h;
        float4 v1 = *(const float4*)(h + HW);
        float4 v2 = *(const float4*)(h + 2 * HW);
        float4 v3 = *(const float4*)(h + 3 * HW);
        float* dst = sC + r0 * BW + cg * 4;
        #pragma unroll
        for (int k = 0; k < 3; k++) {
            float4 v4 = *(const float4*)(h + (4 + k) * HW);
            float4 o;
            o.x = GW0 * (v0.x + v4.x) + GW1 * (v1.x + v3.x) + GW2 * v2.x;
            o.y = GW0 * (v0.y + v4.y) + GW1 * (v1.y + v3.y) + GW2 * v2.y;
            o.z = GW0 * (v0.z + v4.z) + GW1 * (v1.z + v3.z) + GW2 * v2.z;
            o.w = GW0 * (v0.w + v4.w) + GW1 * (v1.w + v3.w) + GW2 * v2.w;
            *(float4*)(dst + k * BW) = o;
            v0 = v1; v1 = v2; v2 = v3; v3 = v4;
        }
    }
    __syncthreads();

    // ---- Phase 4: sobel + octant, rolling 3-row window (17 cg x 12 chunks) ----
    if (interior) {
        if (tid < 17 * 12) {
            int ch = tid / 17;
            int cg = tid - ch * 17;
            int r0 = ch * 3;
            int c0 = cg * 4;
            const float* bp = sC + r0 * BW + c0;
            float a0[8], a1[8], a2[8];
            *(float4*)a0       = *(const float4*)bp;
            *(float4*)(a0 + 4) = *(const float4*)(bp + 4);
            *(float4*)a1       = *(const float4*)(bp + BW);
            *(float4*)(a1 + 4) = *(const float4*)(bp + BW + 4);
            #pragma unroll
            for (int k = 0; k < 3; k++) {
                int r = r0 + k;
                if (r < MH) {
                    *(float4*)a2       = *(const float4*)(bp + (k + 2) * BW);
                    *(float4*)(a2 + 4) = *(const float4*)(bp + (k + 2) * BW + 4);
                    float m[4];
                    uint32_t dpack = 0;
                    #pragma unroll
                    for (int j = 0; j < 4; j++) {
                        float gx = (a0[j+2] - a0[j]) + 2.0f * (a1[j+2] - a1[j]) + (a2[j+2] - a2[j]);
                        float gy = (a2[j]   - a0[j]) + 2.0f * (a2[j+1] - a0[j+1]) + (a2[j+2] - a0[j+2]);
                        float mm = sqrtf(fmaf(gx, gx, fmaf(gy, gy, 1e-6f)));
                        int d = c_nms_off[octant(gx, gy)];
                        if (c0 + j > 65) { mm = 0.0f; d = 1; }   // tile pad cols
                        m[j] = mm;
                        dpack |= ((uint32_t)(uint8_t)(int8_t)d) << (8 * j);
                    }
                    *(float4*)(sM + r * MW + c0) = make_float4(m[0], m[1], m[2], m[3]);
                    sDw[(r * MW + c0) >> 2] = dpack;
                    #pragma unroll
                    for (int j = 0; j < 8; j++) { a0[j] = a1[j]; a1[j] = a2[j]; }
                }
            }
        }
    } else {
        #pragma unroll 1
        for (int i = tid; i < MH * MW; i += NT) {
            int r = i / MW, c = i - r * MW;
            float mm = 0.0f;
            int8_t dch = 1;
            if (c <= 65) {
                int my = y0 - 1 + r;
                int mx = x0 - 1 + c;
                if (my >= 0 && my < H_IMG && mx >= 0 && mx < W_IMG) {
                    int iy0 = max(my - 1, 0)         - (y0 - 2);
                    int iy1 = r + 1;
                    int iy2 = min(my + 1, H_IMG - 1) - (y0 - 2);
                    int ix0 = max(mx - 1, 0)         - (x0 - 2);
                    int ix1 = c + 1;
                    int ix2 = min(mx + 1, W_IMG - 1) - (x0 - 2);
                    float b00 = sC[iy0*BW+ix0], b01 = sC[iy0*BW+ix1], b02 = sC[iy0*BW+ix2];
                    float b10 = sC[iy1*BW+ix0],                       b12 = sC[iy1*BW+ix2];
                    float b20 = sC[iy2*BW+ix0], b21 = sC[iy2*BW+ix1], b22 = sC[iy2*BW+ix2];
                    float gx = (b02 - b00) + 2.0f * (b12 - b10) + (b22 - b20);
                    float gy = (b20 - b00) + 2.0f * (b21 - b01) + (b22 - b02);
                    mm = sqrtf(fmaf(gx, gx, fmaf(gy, gy, 1e-6f)));
                    dch = (int8_t)c_nms_off[octant(gx, gy)];
                }
            }
            sM[i] = mm;
            sD[i] = dch;
        }
    }
    __syncthreads();

    // ---- Phase 5: NMS + vectorized write (TY x 16 float4 items) ----
    float* obase = out + ((size_t)b * H_IMG + y0) * W_IMG + x0;
    #pragma unroll 1
    for (int i = tid; i < TY * 16; i += NT) {
        int r  = i >> 4;
        int c0 = (i & 15) * 4;
        int bse = (r + 1) * MW + c0;              // 16B aligned
        float4 m0 = *(const float4*)(sM + bse);
        float4 m1 = *(const float4*)(sM + bse + 4);
        uint32_t wlo = sDw[bse >> 2];
        uint32_t whi = sDw[(bse >> 2) + 1];
        uint32_t dv  = __funnelshift_r(wlo, whi, 8);  // dirs for cols c0+1..c0+4
        float ctr[4] = { m0.y, m0.z, m0.w, m1.x };
        float res[4];
        #pragma unroll
        for (int j = 0; j < 4; j++) {
            int d = (int)(int8_t)(dv >> (8 * j));
            int lin = bse + 1 + j;
            float mc = ctr[j];
            float sp = mc - sM[lin + d];
            float sn = mc - sM[lin - d];
            res[j] = (fminf(sp, sn) > 0.0f) ? mc : 0.0f;
        }
        *(float4*)(obase + r * W_IMG + c0) = make_float4(res[0], res[1], res[2], res[3]);
    }
}

extern "C" void kernel_launch(void* const* d_in, const int* in_sizes, int n_in,
                              void* d_out, int out_size) {
    const float* in = (const float*)d_in[0];
    float* out = (float*)d_out;
    dim3 grid(W_IMG / TX, H_IMG / TY, 16);   // (8, 16, 16)
    canny_fused_kernel<<<grid, NT>>>(in, out);
}

// round 10
// speedup vs baseline: 1.0432x; 1.0432x over previous
#include <cuda_runtime.h>
#include <stdint.h>

// Canny magnitude, fully fused, float4, smem-aliased (22.6KB) for occupancy.
// gray -> 5x5 separable gaussian (reflect) -> sobel (edge clamp) -> magnitude
// -> comparison octant -> 8-dir NMS (zero pad) -> mag * is_max
// Input (16,3,512,512) f32, output (16,1,512,512) f32.

#define H_IMG 512
#define W_IMG 512
#define PLANE (H_IMG * W_IMG)
#define TX 64
#define TY 32
#define NT 256

#define GW 72   // gray stride (halo 4) = 18 float4
#define GH 40
#define HW 68   // h-blur stride (halo 2) = 17 float4
#define BH 36   // blur rows
#define BW 68   // blur stride (valid cols 0..67; P4 over-reads feed masked lanes)
#define MH 34
#define MW 68   // mag stride (valid cols 0..65; 66,67 pad = 0)

#define SA_F 2880               // gray 40*72; blur 36*68=2448 fits
#define MAG_F (MH * MW)         // 2312 floats
#define SB_F (MAG_F + 578)      // + 578 dir words (2312 bytes)

// idx -> linear NMS offset in mag tile (stride MW=68):
// (0,1)(-1,1)(-1,0)(-1,-1)(0,-1)(1,-1)(1,0)(1,1)
__constant__ int c_nms_off[8] = { 1, -67, -68, -69, -1, 67, 68, 69 };

__device__ __forceinline__ int reflect_idx(int i, int n) {
    if (i < 0) i = -i;
    if (i >= n) i = 2 * n - 2 - i;
    return i;
}

__device__ __forceinline__ int octant(float gx, float gy) {
    // round(atan2(gy,gx)/45deg) mod 8 via comparisons
    float ax = fabsf(gx), ay = fabsf(gy);
    int o = (ay > 0.4142135623730950f * ax) + (ay > 2.4142135623730950f * ax);
    if (gx < 0.0f) return (gy < 0.0f) ? (4 + o) : (4 - o);
    else           return (gy < 0.0f) ? ((8 - o) & 7) : o;
}

#define GQ0 0.054488684548643f
#define GQ1 0.244201342003233f
#define GQ2 0.402619946896247f

__global__ void __launch_bounds__(NT, 7)
canny_fused_kernel(const float* __restrict__ in, float* __restrict__ out) {
    __shared__ __align__(16) float sA[SA_F];   // gray -> blur
    __shared__ __align__(16) float sB[SB_F];   // htmp -> mag + dir words

    float*    sBlur = sA;
    float*    sMag  = sB;
    uint32_t* sDw   = (uint32_t*)(sB + MAG_F);   // 16B-aligned (2312*4 % 16 == 0)
    int8_t*   sDb   = (int8_t*)(sB + MAG_F);

    const int tid = threadIdx.x;
    const int x0  = blockIdx.x * TX;
    const int y0  = blockIdx.y * TY;
    const int b   = blockIdx.z;

    const float* base = in + (size_t)b * 3 * PLANE;

    const bool interior = (x0 >= 4) && (x0 + TX + 4 <= W_IMG) &&
                          (y0 >= 4) && (y0 + TY + 4 <= H_IMG);

    // ---- Phase 1: grayscale into sA (GH x GW) ----
    if (interior) {
        const float* p = base + (y0 - 4) * W_IMG + (x0 - 4);  // 16B aligned
        #pragma unroll 1
        for (int i = tid; i < GH * 18; i += NT) {
            int r = i / 18, c4 = (i - r * 18) * 4;
            const float* q = p + r * W_IMG + c4;
            float4 R = *(const float4*)q;
            float4 G = *(const float4*)(q + PLANE);
            float4 B = *(const float4*)(q + 2 * PLANE);
            float4 o;
            o.x = fmaf(0.1495f, R.x, fmaf(0.2935f, G.x, fmaf(0.057f, B.x, 0.5f)));
            o.y = fmaf(0.1495f, R.y, fmaf(0.2935f, G.y, fmaf(0.057f, B.y, 0.5f)));
            o.z = fmaf(0.1495f, R.z, fmaf(0.2935f, G.z, fmaf(0.057f, B.z, 0.5f)));
            o.w = fmaf(0.1495f, R.w, fmaf(0.2935f, G.w, fmaf(0.057f, B.w, 0.5f)));
            *(float4*)(sA + r * GW + c4) = o;
        }
    } else {
        #pragma unroll 1
        for (int i = tid; i < GH * 18; i += NT) {
            int r = i / 18, c4 = (i - r * 18) * 4;
            int yy = reflect_idx(y0 - 4 + r, H_IMG) * W_IMG;
            float o[4];
            #pragma unroll
            for (int j = 0; j < 4; j++) {
                int off = yy + reflect_idx(x0 - 4 + c4 + j, W_IMG);
                o[j] = fmaf(0.1495f, base[off],
                       fmaf(0.2935f, base[off + PLANE],
                       fmaf(0.057f,  base[off + 2 * PLANE], 0.5f)));
            }
            *(float4*)(sA + r * GW + c4) = make_float4(o[0], o[1], o[2], o[3]);
        }
    }
    __syncthreads();

    // ---- Phase 2: horizontal blur sA(gray) -> sB(htmp, GH x HW) ----
    #pragma unroll 1
    for (int i = tid; i < GH * 17; i += NT) {
        int r = i / 17, c4 = (i - r * 17) * 4;
        const float* g = sA + r * GW + c4;
        float4 a = *(const float4*)g;
        float4 c = *(const float4*)(g + 4);
        float4 o;
        o.x = GQ0 * (a.x + c.x) + GQ1 * (a.y + a.w) + GQ2 * a.z;
        o.y = GQ0 * (a.y + c.y) + GQ1 * (a.z + c.x) + GQ2 * a.w;
        o.z = GQ0 * (a.z + c.z) + GQ1 * (a.w + c.y) + GQ2 * c.x;
        o.w = GQ0 * (a.w + c.w) + GQ1 * (c.x + c.z) + GQ2 * c.y;
        *(float4*)(sB + r * HW + c4) = o;
    }
    __syncthreads();

    // ---- Phase 3: vertical blur sB(htmp) -> sA(blur, BH x BW) ----
    #pragma unroll 1
    for (int i = tid; i < BH * 17; i += NT) {
        int r = i / 17, c4 = (i - r * 17) * 4;
        const float* h = sB + r * HW + c4;
        float4 v0 = *(const float4*)h;
        float4 v1 = *(const float4*)(h + HW);
        float4 v2 = *(const float4*)(h + 2 * HW);
        float4 v3 = *(const float4*)(h + 3 * HW);
        float4 v4 = *(const float4*)(h + 4 * HW);
        float4 o;
        o.x = GQ0 * (v0.x + v4.x) + GQ1 * (v1.x + v3.x) + GQ2 * v2.x;
        o.y = GQ0 * (v0.y + v4.y) + GQ1 * (v1.y + v3.y) + GQ2 * v2.y;
        o.z = GQ0 * (v0.z + v4.z) + GQ1 * (v1.z + v3.z) + GQ2 * v2.z;
        o.w = GQ0 * (v0.w + v4.w) + GQ1 * (v1.w + v3.w) + GQ2 * v2.w;
        *(float4*)(sBlur + r * BW + c4) = o;
    }
    __syncthreads();

    // ---- Phase 4: sobel + octant sA(blur) -> sB(mag + packed dirs) ----
    if (interior) {
        #pragma unroll 1
        for (int i = tid; i < MH * 17; i += NT) {
            int r = i / 17, c0 = (i - r * 17) * 4;
            const float* bp = sBlur + r * BW + c0;
            float t0[8], t1[8], t2[8];
            *(float4*)t0       = *(const float4*)bp;
            *(float4*)(t0 + 4) = *(const float4*)(bp + 4);
            *(float4*)t1       = *(const float4*)(bp + BW);
            *(float4*)(t1 + 4) = *(const float4*)(bp + BW + 4);
            *(float4*)t2       = *(const float4*)(bp + 2 * BW);
            *(float4*)(t2 + 4) = *(const float4*)(bp + 2 * BW + 4);
            float m[4];
            uint32_t dpack = 0;
            #pragma unroll
            for (int j = 0; j < 4; j++) {
                float gx = (t0[j+2] - t0[j]) + 2.0f * (t1[j+2] - t1[j]) + (t2[j+2] - t2[j]);
                float gy = (t2[j]   - t0[j]) + 2.0f * (t2[j+1] - t0[j+1]) + (t2[j+2] - t0[j+2]);
                float mm = sqrtf(fmaf(gx, gx, fmaf(gy, gy, 1e-6f)));
                int d = c_nms_off[octant(gx, gy)];
                if (c0 + j > 65) { mm = 0.0f; d = 1; }   // tile pad cols
                m[j] = mm;
                dpack |= ((uint32_t)(uint8_t)(int8_t)d) << (8 * j);
            }
            *(float4*)(sMag + r * MW + c0) = make_float4(m[0], m[1], m[2], m[3]);
            sDw[(r * MW + c0) >> 2] = dpack;
        }
    } else {
        #pragma unroll 1
        for (int i = tid; i < MH * MW; i += NT) {
            int r = i / MW, c = i - r * MW;
            float mm = 0.0f;
            int8_t dch = 1;
            if (c <= 65) {
                int my = y0 - 1 + r;
                int mx = x0 - 1 + c;
                if (my >= 0 && my < H_IMG && mx >= 0 && mx < W_IMG) {
                    int iy0 = max(my - 1, 0)         - (y0 - 2);
                    int iy1 = r + 1;
                    int iy2 = min(my + 1, H_IMG - 1) - (y0 - 2);
                    int ix0 = max(mx - 1, 0)         - (x0 - 2);
                    int ix1 = c + 1;
                    int ix2 = min(mx + 1, W_IMG - 1) - (x0 - 2);
                    float b00 = sBlur[iy0*BW+ix0], b01 = sBlur[iy0*BW+ix1], b02 = sBlur[iy0*BW+ix2];
                    float b10 = sBlur[iy1*BW+ix0],                          b12 = sBlur[iy1*BW+ix2];
                    float b20 = sBlur[iy2*BW+ix0], b21 = sBlur[iy2*BW+ix1], b22 = sBlur[iy2*BW+ix2];
                    float gx = (b02 - b00) + 2.0f * (b12 - b10) + (b22 - b20);
                    float gy = (b20 - b00) + 2.0f * (b21 - b01) + (b22 - b02);
                    mm = sqrtf(fmaf(gx, gx, fmaf(gy, gy, 1e-6f)));
                    dch = (int8_t)c_nms_off[octant(gx, gy)];
                }
            }
            sMag[i] = mm;
            sDb[i] = dch;
        }
    }
    __syncthreads();

    // ---- Phase 5: NMS + vectorized write (TY x 16 float4 items) ----
    float* obase = out + ((size_t)b * H_IMG + y0) * W_IMG + x0;
    #pragma unroll 1
    for (int i = tid; i < TY * 16; i += NT) {
        int r  = i >> 4;
        int c0 = (i & 15) * 4;
        int bse = (r + 1) * MW + c0;              // 16B aligned
        float4 m0 = *(const float4*)(sMag + bse);
        float4 m1 = *(const float4*)(sMag + bse + 4);
        uint32_t wlo = sDw[bse >> 2];
        uint32_t whi = sDw[(bse >> 2) + 1];
        uint32_t dv  = __funnelshift_r(wlo, whi, 8);  // dirs for cols c0+1..c0+4
        float ctr[4] = { m0.y, m0.z, m0.w, m1.x };
        float res[4];
        #pragma unroll
        for (int j = 0; j < 4; j++) {
            int d = (int)(int8_t)(dv >> (8 * j));
            int lin = bse + 1 + j;
            float mc = ctr[j];
            float sp = mc - sMag[lin + d];
            float sn = mc - sMag[lin - d];
            res[j] = (fminf(sp, sn) > 0.0f) ? mc : 0.0f;
        }
        *(float4*)(obase + r * W_IMG + c0) = make_float4(res[0], res[1], res[2], res[3]);
    }
}

extern "C" void kernel_launch(void* const* d_in, const int* in_sizes, int n_in,
                              void* d_out, int out_size) {
    const float* in = (const float*)d_in[0];
    float* out = (float*)d_out;
    dim3 grid(W_IMG / TX, H_IMG / TY, 16);   // (8, 16, 16)
    canny_fused_kernel<<<grid, NT>>>(in, out);
}

// round 11
// speedup vs baseline: 1.0462x; 1.0029x over previous
#include <cuda_runtime.h>
#include <stdint.h>

// Canny magnitude, fully fused, float4, smem-aliased (22.6KB), arithmetic NMS dir.
// gray -> 5x5 separable gaussian (reflect) -> sobel (edge clamp) -> magnitude
// -> comparison octant (no LUT) -> 8-dir NMS (zero pad) -> mag * is_max
// Input (16,3,512,512) f32, output (16,1,512,512) f32.

#define H_IMG 512
#define W_IMG 512
#define PLANE (H_IMG * W_IMG)
#define TX 64
#define TY 32
#define NT 256

#define GW 72   // gray stride (halo 4) = 18 float4
#define GH 40
#define HW 68   // h-blur stride (halo 2) = 17 float4
#define BH 36   // blur rows
#define BW 68   // blur stride (valid cols 0..67; P4 over-reads feed masked lanes)
#define MH 34
#define MW 68   // mag stride (valid cols 0..65; 66,67 pad = 0)

#define SA_F 2880               // gray 40*72; blur 36*68=2448 fits
#define MAG_F (MH * MW)         // 2312 floats
#define SB_F (MAG_F + 578)      // + 578 dir words (2312 bytes)

__device__ __forceinline__ int reflect_idx(int i, int n) {
    if (i < 0) i = -i;
    if (i >= n) i = 2 * n - 2 - i;
    return i;
}

// NMS linear offset in mag tile (stride 68), no table:
// octant o = round(atan2(gy,gx)/45deg) mod 8 maps to (dy,dx) with
// dx = horizontal-ish component = sign(gx) unless near-vertical,
// dy = -sign(gy) unless near-horizontal;  d = dx + 68*dy.
// Verified against LUT {1,-67,-68,-69,-1,67,68,69} for all octants incl. +-0.
__device__ __forceinline__ int nms_dir(float gx, float gy) {
    float ax = fabsf(gx), ay = fabsf(gy);
    int sx = 1 | (__float_as_int(gx) >> 31);   // sign bit -> +-1 (handles -0)
    int sy = 1 | (__float_as_int(gy) >> 31);
    int dy = (ay > 0.4142135623730950f * ax) ? -sy : 0;
    int dx = (ay > 2.4142135623730950f * ax) ? 0 : sx;
    return dx + 68 * dy;
}

#define GQ0 0.054488684548643f
#define GQ1 0.244201342003233f
#define GQ2 0.402619946896247f

__global__ void __launch_bounds__(NT, 7)
canny_fused_kernel(const float* __restrict__ in, float* __restrict__ out) {
    __shared__ __align__(16) float sA[SA_F];   // gray -> blur
    __shared__ __align__(16) float sB[SB_F];   // htmp -> mag + dir words

    float*    sBlur = sA;
    float*    sMag  = sB;
    uint32_t* sDw   = (uint32_t*)(sB + MAG_F);   // 16B-aligned
    int8_t*   sDb   = (int8_t*)(sB + MAG_F);

    const int tid = threadIdx.x;
    const int x0  = blockIdx.x * TX;
    const int y0  = blockIdx.y * TY;
    const int b   = blockIdx.z;

    const float* base = in + (size_t)b * 3 * PLANE;

    const bool interior = (x0 >= 4) && (x0 + TX + 4 <= W_IMG) &&
                          (y0 >= 4) && (y0 + TY + 4 <= H_IMG);

    // ---- Phase 1: grayscale into sA (GH x GW) ----
    if (interior) {
        const float* p = base + (y0 - 4) * W_IMG + (x0 - 4);  // 16B aligned
        #pragma unroll 1
        for (int i = tid; i < GH * 18; i += NT) {
            int r = i / 18, c4 = (i - r * 18) * 4;
            const float* q = p + r * W_IMG + c4;
            float4 R = *(const float4*)q;
            float4 G = *(const float4*)(q + PLANE);
            float4 B = *(const float4*)(q + 2 * PLANE);
            float4 o;
            o.x = fmaf(0.1495f, R.x, fmaf(0.2935f, G.x, fmaf(0.057f, B.x, 0.5f)));
            o.y = fmaf(0.1495f, R.y, fmaf(0.2935f, G.y, fmaf(0.057f, B.y, 0.5f)));
            o.z = fmaf(0.1495f, R.z, fmaf(0.2935f, G.z, fmaf(0.057f, B.z, 0.5f)));
            o.w = fmaf(0.1495f, R.w, fmaf(0.2935f, G.w, fmaf(0.057f, B.w, 0.5f)));
            *(float4*)(sA + r * GW + c4) = o;
        }
    } else {
        #pragma unroll 1
        for (int i = tid; i < GH * 18; i += NT) {
            int r = i / 18, c4 = (i - r * 18) * 4;
            int yy = reflect_idx(y0 - 4 + r, H_IMG) * W_IMG;
            float o[4];
            #pragma unroll
            for (int j = 0; j < 4; j++) {
                int off = yy + reflect_idx(x0 - 4 + c4 + j, W_IMG);
                o[j] = fmaf(0.1495f, base[off],
                       fmaf(0.2935f, base[off + PLANE],
                       fmaf(0.057f,  base[off + 2 * PLANE], 0.5f)));
            }
            *(float4*)(sA + r * GW + c4) = make_float4(o[0], o[1], o[2], o[3]);
        }
    }
    __syncthreads();

    // ---- Phase 2: horizontal blur sA(gray) -> sB(htmp, GH x HW) ----
    #pragma unroll 1
    for (int i = tid; i < GH * 17; i += NT) {
        int r = i / 17, c4 = (i - r * 17) * 4;
        const float* g = sA + r * GW + c4;
        float4 a = *(const float4*)g;
        float4 c = *(const float4*)(g + 4);
        float4 o;
        o.x = GQ0 * (a.x + c.x) + GQ1 * (a.y + a.w) + GQ2 * a.z;
        o.y = GQ0 * (a.y + c.y) + GQ1 * (a.z + c.x) + GQ2 * a.w;
        o.z = GQ0 * (a.z + c.z) + GQ1 * (a.w + c.y) + GQ2 * c.x;
        o.w = GQ0 * (a.w + c.w) + GQ1 * (c.x + c.z) + GQ2 * c.y;
        *(float4*)(sB + r * HW + c4) = o;
    }
    __syncthreads();

    // ---- Phase 3: vertical blur sB(htmp) -> sA(blur, BH x BW) ----
    #pragma unroll 1
    for (int i = tid; i < BH * 17; i += NT) {
        int r = i / 17, c4 = (i - r * 17) * 4;
        const float* h = sB + r * HW + c4;
        float4 v0 = *(const float4*)h;
        float4 v1 = *(const float4*)(h + HW);
        float4 v2 = *(const float4*)(h + 2 * HW);
        float4 v3 = *(const float4*)(h + 3 * HW);
        float4 v4 = *(const float4*)(h + 4 * HW);
        float4 o;
        o.x = GQ0 * (v0.x + v4.x) + GQ1 * (v1.x + v3.x) + GQ2 * v2.x;
        o.y = GQ0 * (v0.y + v4.y) + GQ1 * (v1.y + v3.y) + GQ2 * v2.y;
        o.z = GQ0 * (v0.z + v4.z) + GQ1 * (v1.z + v3.z) + GQ2 * v2.z;
        o.w = GQ0 * (v0.w + v4.w) + GQ1 * (v1.w + v3.w) + GQ2 * v2.w;
        *(float4*)(sBlur + r * BW + c4) = o;
    }
    __syncthreads();

    // ---- Phase 4: sobel + arithmetic dir, sA(blur) -> sB(mag + packed dirs) ----
    if (interior) {
        #pragma unroll 1
        for (int i = tid; i < MH * 17; i += NT) {
            int r = i / 17, c0 = (i - r * 17) * 4;
            const float* bp = sBlur + r * BW + c0;
            float t0[8], t1[8], t2[8];
            *(float4*)t0       = *(const float4*)bp;
            *(float4*)(t0 + 4) = *(const float4*)(bp + 4);
            *(float4*)t1       = *(const float4*)(bp + BW);
            *(float4*)(t1 + 4) = *(const float4*)(bp + BW + 4);
            *(float4*)t2       = *(const float4*)(bp + 2 * BW);
            *(float4*)(t2 + 4) = *(const float4*)(bp + 2 * BW + 4);
            float m[4];
            uint32_t dpack = 0;
            #pragma unroll
            for (int j = 0; j < 4; j++) {
                float gx = (t0[j+2] - t0[j]) + 2.0f * (t1[j+2] - t1[j]) + (t2[j+2] - t2[j]);
                float gy = (t2[j]   - t0[j]) + 2.0f * (t2[j+1] - t0[j+1]) + (t2[j+2] - t0[j+2]);
                float mm = sqrtf(fmaf(gx, gx, fmaf(gy, gy, 1e-6f)));
                int d = nms_dir(gx, gy);
                if (c0 + j > 65) { mm = 0.0f; d = 1; }   // tile pad cols
                m[j] = mm;
                dpack |= ((uint32_t)(uint8_t)(int8_t)d) << (8 * j);
            }
            *(float4*)(sMag + r * MW + c0) = make_float4(m[0], m[1], m[2], m[3]);
            sDw[(r * MW + c0) >> 2] = dpack;
        }
    } else {
        #pragma unroll 1
        for (int i = tid; i < MH * MW; i += NT) {
            int r = i / MW, c = i - r * MW;
            float mm = 0.0f;
            int8_t dch = 1;
            if (c <= 65) {
                int my = y0 - 1 + r;
                int mx = x0 - 1 + c;
                if (my >= 0 && my < H_IMG && mx >= 0 && mx < W_IMG) {
                    int iy0 = max(my - 1, 0)         - (y0 - 2);
                    int iy1 = r + 1;
                    int iy2 = min(my + 1, H_IMG - 1) - (y0 - 2);
                    int ix0 = max(mx - 1, 0)         - (x0 - 2);
                    int ix1 = c + 1;
                    int ix2 = min(mx + 1, W_IMG - 1) - (x0 - 2);
                    float b00 = sBlur[iy0*BW+ix0], b01 = sBlur[iy0*BW+ix1], b02 = sBlur[iy0*BW+ix2];
                    float b10 = sBlur[iy1*BW+ix0],                          b12 = sBlur[iy1*BW+ix2];
                    float b20 = sBlur[iy2*BW+ix0], b21 = sBlur[iy2*BW+ix1], b22 = sBlur[iy2*BW+ix2];
                    float gx = (b02 - b00) + 2.0f * (b12 - b10) + (b22 - b20);
                    float gy = (b20 - b00) + 2.0f * (b21 - b01) + (b22 - b02);
                    mm = sqrtf(fmaf(gx, gx, fmaf(gy, gy, 1e-6f)));
                    dch = (int8_t)nms_dir(gx, gy);
                }
            }
            sMag[i] = mm;
            sDb[i] = dch;
        }
    }
    __syncthreads();

    // ---- Phase 5: NMS + vectorized write (exactly 2 items/thread) ----
    float* obase = out + ((size_t)b * H_IMG + y0) * W_IMG + x0;
    #pragma unroll
    for (int it = 0; it < 2; it++) {
        int i  = tid + it * NT;                   // 0..511
        int r  = i >> 4;
        int c0 = (i & 15) * 4;
        int bse = (r + 1) * MW + c0;              // 16B aligned
        float4 m0 = *(const float4*)(sMag + bse);
        float4 m1 = *(const float4*)(sMag + bse + 4);
        uint32_t wlo = sDw[bse >> 2];
        uint32_t whi = sDw[(bse >> 2) + 1];
        uint32_t dv  = __funnelshift_r(wlo, whi, 8);  // dirs for cols c0+1..c0+4
        float ctr[4] = { m0.y, m0.z, m0.w, m1.x };
        float res[4];
        #pragma unroll
        for (int j = 0; j < 4; j++) {
            int d = (int)(int8_t)(dv >> (8 * j));
            int lin = bse + 1 + j;
            float mc = ctr[j];
            float sp = mc - sMag[lin + d];
            float sn = mc - sMag[lin - d];
            res[j] = (fminf(sp, sn) > 0.0f) ? mc : 0.0f;
        }
        *(float4*)(obase + r * W_IMG + c0) = make_float4(res[0], res[1], res[2], res[3]);
    }
}

extern "C" void kernel_launch(void* const* d_in, const int* in_sizes, int n_in,
                              void* d_out, int out_size) {
    const float* in = (const float*)d_in[0];
    float* out = (float*)d_out;
    dim3 grid(W_IMG / TX, H_IMG / TY, 16);   // (8, 16, 16)
    canny_fused_kernel<<<grid, NT>>>(in, out);
}